// round 11
// baseline (speedup 1.0000x reference)
#include <cuda_runtime.h>
#include <math.h>

// ---------------------------------------------------------------------------
// ImageSectionRNNCell — B=64, image 512x512x3, grid 16x16, U=256
// out layout: h_new[64*256] | c_new[64*256] | next_section[64*3]
//
// 4 launches (split-K + last-block finisher, counters self-reset):
//  K1 (64):  front (interp+conv1+conv2 -> g_xs) + bias-init g_y/g_ns
//  K2 (128): dense partial xs@dw -> g_y (atomicAdd, bias-pre-init)
//  K3 (128): LSTM partial (32 col-tile x 4 k-tile) -> g_zp (unit-major);
//            last block per 32-unit slice computes gates -> out h/c
//  K5 (128): nsc1 partial h@w1 -> g_ns (atomicAdd, bias-pre-init);
//            last block overall computes nsc2 -> out section
// ---------------------------------------------------------------------------

#define B 64
#define U 256
#define IMGH 512
#define IMGW 512

__device__ float g_xs[B * 432];        // conv2 output (dense input)
__device__ float g_y [B * U];          // dense pre-act accumulator (bias-init)
__device__ float g_zp[4][B][4 * U];    // LSTM partials, unit-major [b][u*4+g]
__device__ float g_ns[B * U];          // nsc1 pre-act accumulator (bias-init)

__device__ unsigned g_cnt_z[8][32];    // per unit-slice counters (128B rows)
__device__ unsigned g_cnt_ns[32];      // nsc1 completion counter

__device__ __forceinline__ float sigmoidf_(float x) {
    return 1.0f / (1.0f + __expf(-x));
}

// ===========================================================================
// K1: bias-init g_y/g_ns + interpolate + conv1 + conv2 -> g_xs
// ===========================================================================
__global__ __launch_bounds__(256, 4)
void k1_front(const float* __restrict__ image,
              const float* __restrict__ section,
              const float* __restrict__ c1k, const float* __restrict__ c1b,
              const float* __restrict__ c2k, const float* __restrict__ c2b,
              const float* __restrict__ db,  const float* __restrict__ b1)
{
    const int b = blockIdx.x;
    const int t = threadIdx.x;

    g_y [b * U + t] = db[t];
    g_ns[b * U + t] = b1[t];

    __shared__ float sec[16 * 16 * 3];
    __shared__ float c1o[14 * 14 * 3];

    {
        const float s0 = section[b * 3 + 0];
        const float s1 = section[b * 3 + 1];
        const float ee = section[b * 3 + 2];
        const int i = t >> 4;
        const int j = t & 15;
        const float p0 = s0 + (float)i * (1.0f / 15.0f) * ee;
        const float p1 = s1 + (float)j * (1.0f / 15.0f) * ee;
        float fy = fminf(fmaxf(p0 * (float)(IMGH - 1), 0.0f), (float)(IMGH - 1));
        float fx = fminf(fmaxf(p1 * (float)(IMGW - 1), 0.0f), (float)(IMGW - 1));
        int y0 = (int)floorf(fy);
        int x0 = (int)floorf(fx);
        int y1 = min(y0 + 1, IMGH - 1);
        int x1 = min(x0 + 1, IMGW - 1);
        float wy = fy - (float)y0;
        float wx = fx - (float)x0;
        const float* img = image + (size_t)b * IMGH * IMGW * 3;
        const float* p00 = img + ((size_t)y0 * IMGW + x0) * 3;
        const float* p01 = img + ((size_t)y0 * IMGW + x1) * 3;
        const float* p10 = img + ((size_t)y1 * IMGW + x0) * 3;
        const float* p11 = img + ((size_t)y1 * IMGW + x1) * 3;
        #pragma unroll
        for (int c = 0; c < 3; c++) {
            float top = p00[c] * (1.0f - wx) + p01[c] * wx;
            float bot = p10[c] * (1.0f - wx) + p11[c] * wx;
            sec[(i * 16 + j) * 3 + c] = top * (1.0f - wy) + bot * wy;
        }
    }
    __syncthreads();

    if (t < 196) {
        const int oh = t / 14;
        const int ow = t - oh * 14;
        float a0 = c1b[0], a1 = c1b[1], a2 = c1b[2];
        #pragma unroll
        for (int kh = 0; kh < 3; kh++)
            #pragma unroll
            for (int kw = 0; kw < 3; kw++) {
                const float* s = &sec[((oh + kh) * 16 + (ow + kw)) * 3];
                const float* w = &c1k[(kh * 3 + kw) * 9];
                #pragma unroll
                for (int ic = 0; ic < 3; ic++) {
                    const float sv = s[ic];
                    a0 += sv * w[ic * 3 + 0];
                    a1 += sv * w[ic * 3 + 1];
                    a2 += sv * w[ic * 3 + 2];
                }
            }
        c1o[t * 3 + 0] = fmaxf(a0, 0.0f);
        c1o[t * 3 + 1] = fmaxf(a1, 0.0f);
        c1o[t * 3 + 2] = fmaxf(a2, 0.0f);
    }
    __syncthreads();

    if (t < 144) {
        const int oh = t / 12;
        const int ow = t - oh * 12;
        float a0 = c2b[0], a1 = c2b[1], a2 = c2b[2];
        #pragma unroll
        for (int kh = 0; kh < 3; kh++)
            #pragma unroll
            for (int kw = 0; kw < 3; kw++) {
                const float* s = &c1o[((oh + kh) * 14 + (ow + kw)) * 3];
                const float* w = &c2k[(kh * 3 + kw) * 9];
                #pragma unroll
                for (int ic = 0; ic < 3; ic++) {
                    const float sv = s[ic];
                    a0 += sv * w[ic * 3 + 0];
                    a1 += sv * w[ic * 3 + 1];
                    a2 += sv * w[ic * 3 + 2];
                }
            }
        float* dst = g_xs + b * 432 + t * 3;
        dst[0] = fmaxf(a0, 0.0f);
        dst[1] = fmaxf(a1, 0.0f);
        dst[2] = fmaxf(a2, 0.0f);
    }
}

// ===========================================================================
// K2: dense partial. 128 blocks = 32 unit-tiles (8 units) x 4 k-tiles (108).
// atomicAdd into g_y (bias pre-initialized). ReLU applied by consumer (K3).
// ===========================================================================
__global__ __launch_bounds__(256, 1)
void k2_dense(const float* __restrict__ dw)
{
    const int ut = blockIdx.x & 31;
    const int kt = blockIdx.x >> 5;
    const int t  = threadIdx.x;
    const int k0 = kt * 108;

    __shared__ float axs[64][112];
    __shared__ float wts[108][12];

    for (int i = t; i < 64 * 27; i += 256) {
        const int row = i / 27;
        const int c4  = i - row * 27;
        const float4 v = *(const float4*)(g_xs + row * 432 + k0 + c4 * 4);
        *(float4*)&axs[row][c4 * 4] = v;
    }
    if (t < 216) {
        const int row = t >> 1;
        const int h   = t & 1;
        const float4 w = *(const float4*)(dw + (size_t)(k0 + row) * U + ut * 8 + h * 4);
        *(float4*)&wts[row][h * 4] = w;
    }
    __syncthreads();

    const int u2 = t & 3;
    const int bp = t >> 2;
    float a0 = 0.f, a1 = 0.f, a2 = 0.f, a3 = 0.f;
    #pragma unroll 2
    for (int k = 0; k < 108; k += 2) {
        const float x0 = axs[bp][k];
        const float x1 = axs[bp][k + 1];
        const float2 w0 = *(const float2*)&wts[k][u2 * 2];
        const float2 w1 = *(const float2*)&wts[k + 1][u2 * 2];
        a0 += x0 * w0.x; a1 += x0 * w0.y;
        a2 += x1 * w1.x; a3 += x1 * w1.y;
    }
    const int u = ut * 8 + u2 * 2;
    atomicAdd(&g_y[bp * U + u],     a0 + a2);
    atomicAdd(&g_y[bp * U + u + 1], a1 + a3);
}

// ===========================================================================
// K3: LSTM partial + fused gate finisher.
// 128 blocks = 32 col-tiles (ct) x 4 k-tiles (kt).
//   kt<2 : acts = relu(g_y), weights = lstm_k
//   kt>=2: acts = h0,        weights = lstm_rk
// Partials -> g_zp[kt], unit-major [b][u*4+gate]. Unit-slice us = ct&7 is fed
// by 16 blocks (4 ct-groups x 4 kt); the 16th to arrive computes the gates
// for its 32 units x 64 batches and writes h_new/c_new.
// Dynamic smem: act[64][132] + wt[128][36] = 52224 bytes.
// ===========================================================================
__global__ __launch_bounds__(256, 1)
void k3_lstm(const float* __restrict__ h0, const float* __restrict__ c0in,
             const float* __restrict__ lk, const float* __restrict__ lrk,
             const float* __restrict__ lb, float* __restrict__ out)
{
    extern __shared__ float dsm[];
    float (*act)[132] = (float(*)[132])dsm;               // 64 x 132
    float (*wt)[36]   = (float(*)[36])(dsm + 64 * 132);   // 128 x 36
    __shared__ unsigned s_old;

    const int ct = blockIdx.x & 31;
    const int kt = blockIdx.x >> 5;
    const int t  = threadIdx.x;

    if (kt < 2) {
        const float* base = g_y + kt * 128;
        for (int i = t; i < 64 * 32; i += 256) {
            const int row = i >> 5;
            const int c4  = i & 31;
            float4 v = *(const float4*)(base + row * U + c4 * 4);
            v.x = fmaxf(v.x, 0.f); v.y = fmaxf(v.y, 0.f);
            v.z = fmaxf(v.z, 0.f); v.w = fmaxf(v.w, 0.f);
            *(float4*)&act[row][c4 * 4] = v;
        }
    } else {
        const float* base = h0 + (kt - 2) * 128;
        for (int i = t; i < 64 * 32; i += 256) {
            const int row = i >> 5;
            const int c4  = i & 31;
            const float4 v = *(const float4*)(base + row * U + c4 * 4);
            *(float4*)&act[row][c4 * 4] = v;
        }
    }
    {
        const float* wsrc = (kt < 2) ? (lk + (size_t)kt * 128 * 1024)
                                     : (lrk + (size_t)(kt - 2) * 128 * 1024);
        for (int i = t; i < 128 * 8; i += 256) {
            const int row = i >> 3;
            const int c4  = i & 7;
            const float4 w = *(const float4*)(wsrc + (size_t)row * 1024 + ct * 32 + c4 * 4);
            *(float4*)&wt[row][c4 * 4] = w;
        }
    }
    __syncthreads();

    const int c4 = t & 7;        // 4 cols: ct*32 + c4*4 ..
    const int bp = t >> 3;       // batches bp, bp+32
    float s00 = 0.f, s01 = 0.f, s02 = 0.f, s03 = 0.f;
    float s10 = 0.f, s11 = 0.f, s12 = 0.f, s13 = 0.f;
    #pragma unroll 4
    for (int k = 0; k < 128; k++) {
        const float a0 = act[bp][k];
        const float a1 = act[bp + 32][k];
        const float4 w = *(const float4*)&wt[k][c4 * 4];
        s00 += a0 * w.x; s01 += a0 * w.y; s02 += a0 * w.z; s03 += a0 * w.w;
        s10 += a1 * w.x; s11 += a1 * w.y; s12 += a1 * w.z; s13 += a1 * w.w;
    }
    // unit-major scatter: col = ct*32 + c4*4 + q -> [b][(u0+q)*4 + gate]
    const int col = ct * 32 + c4 * 4;
    const int gg  = col >> 8;        // gate index 0..3
    const int u0  = col & 255;       // unit index
    float* d0 = &g_zp[kt][bp][u0 * 4 + gg];
    d0[0]  = s00; d0[4]  = s01; d0[8]  = s02; d0[12] = s03;
    float* d1 = &g_zp[kt][bp + 32][u0 * 4 + gg];
    d1[0]  = s10; d1[4]  = s11; d1[8]  = s12; d1[12] = s13;

    // ---- arrival + last-block gate finisher ----
    const int us = ct & 7;           // unit slice: units [us*32, us*32+32)
    __threadfence();
    __syncthreads();
    if (t == 0) {
        const unsigned old = atomicAdd(&g_cnt_z[us][0], 1);
        s_old = old;
        if (old == 15) g_cnt_z[us][0] = 0;   // reset for next replay
    }
    __syncthreads();
    if (s_old != 15) return;

    __threadfence();
    #pragma unroll
    for (int p = t; p < 2048; p += 256) {
        const int b = p >> 5;
        const int u = us * 32 + (p & 31);
        const float4 z0 = __ldcg((const float4*)&g_zp[0][b][u * 4]);
        const float4 z1 = __ldcg((const float4*)&g_zp[1][b][u * 4]);
        const float4 z2 = __ldcg((const float4*)&g_zp[2][b][u * 4]);
        const float4 z3 = __ldcg((const float4*)&g_zp[3][b][u * 4]);
        const float zi = z0.x + z1.x + z2.x + z3.x + lb[u];
        const float zf = z0.y + z1.y + z2.y + z3.y + lb[U + u];
        const float zg = z0.z + z1.z + z2.z + z3.z + lb[2 * U + u];
        const float zo = z0.w + z1.w + z2.w + z3.w + lb[3 * U + u];
        const float cprev = c0in[b * U + u];
        const float cn = sigmoidf_(zf) * cprev + sigmoidf_(zi) * tanhf(zg);
        const float hn = sigmoidf_(zo) * tanhf(cn);
        out[b * U + u]         = hn;
        out[B * U + b * U + u] = cn;
    }
}

// ===========================================================================
// K5: nsc1 partial + fused nsc2 finisher.
// 128 blocks = 32 unit-tiles (8 units) x 4 k-tiles (64). acts = h_new.
// atomicAdd into g_ns (bias pre-init). Last of the 128 blocks computes
// next_section = sigmoid(relu(g_ns) @ W2 + b2) and resets the counter.
// ===========================================================================
__global__ __launch_bounds__(256, 1)
void k5_nsc1(const float* __restrict__ w1, const float* __restrict__ w2,
             const float* __restrict__ b2, float* __restrict__ out)
{
    const int ut = blockIdx.x & 31;
    const int kt = blockIdx.x >> 5;      // 0..3, k-slice of 64
    const int t  = threadIdx.x;
    const int k0 = kt * 64;

    __shared__ float axs[64][68];
    __shared__ float wts[64][12];
    __shared__ unsigned s_old;

    for (int i = t; i < 64 * 16; i += 256) {
        const int row = i >> 4;
        const int c4  = i & 15;
        const float4 v = *(const float4*)(out + row * U + k0 + c4 * 4);
        *(float4*)&axs[row][c4 * 4] = v;
    }
    if (t < 128) {
        const int row = t >> 1;
        const int h   = t & 1;
        const float4 w = *(const float4*)(w1 + (size_t)(k0 + row) * U + ut * 8 + h * 4);
        *(float4*)&wts[row][h * 4] = w;
    }
    __syncthreads();

    const int u2 = t & 3;
    const int bp = t >> 2;
    float a0 = 0.f, a1 = 0.f, a2 = 0.f, a3 = 0.f;
    #pragma unroll 4
    for (int k = 0; k < 64; k += 2) {
        const float x0 = axs[bp][k];
        const float x1 = axs[bp][k + 1];
        const float2 w0 = *(const float2*)&wts[k][u2 * 2];
        const float2 w1v = *(const float2*)&wts[k + 1][u2 * 2];
        a0 += x0 * w0.x;  a1 += x0 * w0.y;
        a2 += x1 * w1v.x; a3 += x1 * w1v.y;
    }
    const int u = ut * 8 + u2 * 2;
    atomicAdd(&g_ns[bp * U + u],     a0 + a2);
    atomicAdd(&g_ns[bp * U + u + 1], a1 + a3);

    // ---- arrival + last-block nsc2 finisher ----
    __threadfence();
    __syncthreads();
    if (t == 0) {
        const unsigned old = atomicAdd(&g_cnt_ns[0], 1);
        s_old = old;
        if (old == 127) g_cnt_ns[0] = 0;     // reset for next replay
    }
    __syncthreads();
    if (s_old != 127) return;

    __threadfence();
    const int w = t >> 5;          // warp 0..7
    const int l = t & 31;
    for (int b = w; b < B; b += 8) {
        float s0 = 0.f, s1 = 0.f, s2 = 0.f;
        #pragma unroll
        for (int i = 0; i < 8; i++) {
            const int k = l + i * 32;
            const float v = fmaxf(__ldcg(&g_ns[b * U + k]), 0.0f);
            s0 += v * w2[k * 3 + 0];
            s1 += v * w2[k * 3 + 1];
            s2 += v * w2[k * 3 + 2];
        }
        #pragma unroll
        for (int o = 16; o > 0; o >>= 1) {
            s0 += __shfl_down_sync(0xffffffffu, s0, o);
            s1 += __shfl_down_sync(0xffffffffu, s1, o);
            s2 += __shfl_down_sync(0xffffffffu, s2, o);
        }
        if (l == 0) {
            out[2 * B * U + b * 3 + 0] = sigmoidf_(s0 + b2[0]);
            out[2 * B * U + b * 3 + 1] = sigmoidf_(s1 + b2[1]);
            out[2 * B * U + b * 3 + 2] = sigmoidf_(s2 + b2[2]);
        }
    }
}

// ===========================================================================
extern "C" void kernel_launch(void* const* d_in, const int* in_sizes, int n_in,
                              void* d_out, int out_size)
{
    const float* image   = (const float*)d_in[0];
    const float* section = (const float*)d_in[1];
    const float* h0      = (const float*)d_in[2];
    const float* c0      = (const float*)d_in[3];
    const float* conv1_k = (const float*)d_in[4];
    const float* conv1_b = (const float*)d_in[5];
    const float* conv2_k = (const float*)d_in[6];
    const float* conv2_b = (const float*)d_in[7];
    const float* dense_w = (const float*)d_in[8];
    const float* dense_b = (const float*)d_in[9];
    const float* lstm_k  = (const float*)d_in[10];
    const float* lstm_rk = (const float*)d_in[11];
    const float* lstm_b  = (const float*)d_in[12];
    const float* nsc_w1  = (const float*)d_in[13];
    const float* nsc_b1  = (const float*)d_in[14];
    const float* nsc_w2  = (const float*)d_in[15];
    const float* nsc_b2  = (const float*)d_in[16];
    float* out = (float*)d_out;

    static int attr_done = 0;
    if (!attr_done) {
        cudaFuncSetAttribute(k3_lstm,
                             cudaFuncAttributeMaxDynamicSharedMemorySize,
                             64 * 1024);
        attr_done = 1;
    }

    k1_front<<<B, 256>>>(image, section, conv1_k, conv1_b,
                         conv2_k, conv2_b, dense_b, nsc_b1);
    k2_dense<<<128, 256>>>(dense_w);
    k3_lstm<<<128, 256, (64 * 132 + 128 * 36) * 4>>>(h0, c0, lstm_k, lstm_rk,
                                                     lstm_b, out);
    k5_nsc1<<<128, 256>>>(nsc_w1, nsc_w2, nsc_b2, out);
}

// round 12
// speedup vs baseline: 1.4416x; 1.4416x over previous
#include <cuda_runtime.h>
#include <math.h>

// ---------------------------------------------------------------------------
// ImageSectionRNNCell — B=64, image 512x512x3, grid 16x16, U=256
// out layout: h_new[64*256] | c_new[64*256] | next_section[64*3]
//
// 6 launches (R7 structure; k3 re-tiled 64cols x 64k to cut LDG issue):
//  K1 (64):      front (interp+conv1+conv2 -> g_xs) + bias-init g_y/g_ns
//  K2 (128):     dense partial xs@dw -> g_y (atomicAdd, bias-pre-init)
//  K3 (128):     LSTM partial (16 col-tile x 8 k-tile) -> g_zp (unit-major)
//  K4 (128x128): gates: sum 8 g_zp slices + lb, nonlinearity -> out h/c
//  K5 (128):     nsc1 partial h@w1 -> g_ns (atomicAdd, bias-pre-init)
//  K6 (64):      nsc2 -> out section
// ---------------------------------------------------------------------------

#define B 64
#define U 256
#define IMGH 512
#define IMGW 512

__device__ float g_xs[B * 432];        // conv2 output (dense input)
__device__ float g_y [B * U];          // dense pre-act accumulator (bias-init)
__device__ float g_zp[8][B][4 * U];    // LSTM partials, unit-major [b][u*4+g]
__device__ float g_ns[B * U];          // nsc1 pre-act accumulator (bias-init)

__device__ __forceinline__ float sigmoidf_(float x) {
    return 1.0f / (1.0f + __expf(-x));
}

// ===========================================================================
// K1: bias-init g_y/g_ns + interpolate + conv1 + conv2 -> g_xs
// ===========================================================================
__global__ __launch_bounds__(256, 4)
void k1_front(const float* __restrict__ image,
              const float* __restrict__ section,
              const float* __restrict__ c1k, const float* __restrict__ c1b,
              const float* __restrict__ c2k, const float* __restrict__ c2b,
              const float* __restrict__ db,  const float* __restrict__ b1)
{
    const int b = blockIdx.x;
    const int t = threadIdx.x;

    g_y [b * U + t] = db[t];
    g_ns[b * U + t] = b1[t];

    __shared__ float sec[16 * 16 * 3];
    __shared__ float c1o[14 * 14 * 3];

    {
        const float s0 = section[b * 3 + 0];
        const float s1 = section[b * 3 + 1];
        const float ee = section[b * 3 + 2];
        const int i = t >> 4;
        const int j = t & 15;
        const float p0 = s0 + (float)i * (1.0f / 15.0f) * ee;
        const float p1 = s1 + (float)j * (1.0f / 15.0f) * ee;
        float fy = fminf(fmaxf(p0 * (float)(IMGH - 1), 0.0f), (float)(IMGH - 1));
        float fx = fminf(fmaxf(p1 * (float)(IMGW - 1), 0.0f), (float)(IMGW - 1));
        int y0 = (int)floorf(fy);
        int x0 = (int)floorf(fx);
        int y1 = min(y0 + 1, IMGH - 1);
        int x1 = min(x0 + 1, IMGW - 1);
        float wy = fy - (float)y0;
        float wx = fx - (float)x0;
        const float* img = image + (size_t)b * IMGH * IMGW * 3;
        const float* p00 = img + ((size_t)y0 * IMGW + x0) * 3;
        const float* p01 = img + ((size_t)y0 * IMGW + x1) * 3;
        const float* p10 = img + ((size_t)y1 * IMGW + x0) * 3;
        const float* p11 = img + ((size_t)y1 * IMGW + x1) * 3;
        #pragma unroll
        for (int c = 0; c < 3; c++) {
            float top = p00[c] * (1.0f - wx) + p01[c] * wx;
            float bot = p10[c] * (1.0f - wx) + p11[c] * wx;
            sec[(i * 16 + j) * 3 + c] = top * (1.0f - wy) + bot * wy;
        }
    }
    __syncthreads();

    if (t < 196) {
        const int oh = t / 14;
        const int ow = t - oh * 14;
        float a0 = c1b[0], a1 = c1b[1], a2 = c1b[2];
        #pragma unroll
        for (int kh = 0; kh < 3; kh++)
            #pragma unroll
            for (int kw = 0; kw < 3; kw++) {
                const float* s = &sec[((oh + kh) * 16 + (ow + kw)) * 3];
                const float* w = &c1k[(kh * 3 + kw) * 9];
                #pragma unroll
                for (int ic = 0; ic < 3; ic++) {
                    const float sv = s[ic];
                    a0 += sv * w[ic * 3 + 0];
                    a1 += sv * w[ic * 3 + 1];
                    a2 += sv * w[ic * 3 + 2];
                }
            }
        c1o[t * 3 + 0] = fmaxf(a0, 0.0f);
        c1o[t * 3 + 1] = fmaxf(a1, 0.0f);
        c1o[t * 3 + 2] = fmaxf(a2, 0.0f);
    }
    __syncthreads();

    if (t < 144) {
        const int oh = t / 12;
        const int ow = t - oh * 12;
        float a0 = c2b[0], a1 = c2b[1], a2 = c2b[2];
        #pragma unroll
        for (int kh = 0; kh < 3; kh++)
            #pragma unroll
            for (int kw = 0; kw < 3; kw++) {
                const float* s = &c1o[((oh + kh) * 14 + (ow + kw)) * 3];
                const float* w = &c2k[(kh * 3 + kw) * 9];
                #pragma unroll
                for (int ic = 0; ic < 3; ic++) {
                    const float sv = s[ic];
                    a0 += sv * w[ic * 3 + 0];
                    a1 += sv * w[ic * 3 + 1];
                    a2 += sv * w[ic * 3 + 2];
                }
            }
        float* dst = g_xs + b * 432 + t * 3;
        dst[0] = fmaxf(a0, 0.0f);
        dst[1] = fmaxf(a1, 0.0f);
        dst[2] = fmaxf(a2, 0.0f);
    }
}

// ===========================================================================
// K2: dense partial. 128 blocks = 32 unit-tiles (8 units) x 4 k-tiles (108).
// atomicAdd into g_y (bias pre-initialized). ReLU applied by consumer (K3).
// ===========================================================================
__global__ __launch_bounds__(256, 1)
void k2_dense(const float* __restrict__ dw)
{
    const int ut = blockIdx.x & 31;
    const int kt = blockIdx.x >> 5;
    const int t  = threadIdx.x;
    const int k0 = kt * 108;

    __shared__ float axs[64][112];
    __shared__ float wts[108][12];

    for (int i = t; i < 64 * 27; i += 256) {
        const int row = i / 27;
        const int c4  = i - row * 27;
        const float4 v = *(const float4*)(g_xs + row * 432 + k0 + c4 * 4);
        *(float4*)&axs[row][c4 * 4] = v;
    }
    if (t < 216) {
        const int row = t >> 1;
        const int h   = t & 1;
        const float4 w = *(const float4*)(dw + (size_t)(k0 + row) * U + ut * 8 + h * 4);
        *(float4*)&wts[row][h * 4] = w;
    }
    __syncthreads();

    const int u2 = t & 3;
    const int bp = t >> 2;
    float a0 = 0.f, a1 = 0.f, a2 = 0.f, a3 = 0.f;
    #pragma unroll 2
    for (int k = 0; k < 108; k += 2) {
        const float x0 = axs[bp][k];
        const float x1 = axs[bp][k + 1];
        const float2 w0 = *(const float2*)&wts[k][u2 * 2];
        const float2 w1 = *(const float2*)&wts[k + 1][u2 * 2];
        a0 += x0 * w0.x; a1 += x0 * w0.y;
        a2 += x1 * w1.x; a3 += x1 * w1.y;
    }
    const int u = ut * 8 + u2 * 2;
    atomicAdd(&g_y[bp * U + u],     a0 + a2);
    atomicAdd(&g_y[bp * U + u + 1], a1 + a3);
}

// ===========================================================================
// K3: LSTM partial. 128 blocks = 16 col-tiles (64 z-cols) x 8 k-tiles (64).
//   kt<4 : acts = relu(g_y[:, kt*64:]),  weights = lstm_k
//   kt>=4: acts = h0[:, (kt-4)*64:],     weights = lstm_rk
// Per block: act 1024 LDG.128 + wt 1024 LDG.128 (vs 3072 in the 32x128 tile).
// Thread = (col-group c4 0..15, batch-group bq 0..15) -> 4 cols x 4 batches.
// Partials -> g_zp[kt], unit-major [b][u*4+gate] (plain stores).
// ===========================================================================
__global__ __launch_bounds__(256, 1)
void k3_lstm(const float* __restrict__ h0,
             const float* __restrict__ lk, const float* __restrict__ lrk)
{
    __shared__ float act[64][68];   // [batch][k]
    __shared__ float wt [64][68];   // [k][col]

    const int ct = blockIdx.x & 15;
    const int kt = blockIdx.x >> 4;
    const int t  = threadIdx.x;

    // ---- load act slice: 64 batches x 64 k ----
    if (kt < 4) {
        const float* base = g_y + kt * 64;
        for (int i = t; i < 64 * 16; i += 256) {
            const int row = i >> 4;
            const int c4  = i & 15;
            float4 v = *(const float4*)(base + row * U + c4 * 4);
            v.x = fmaxf(v.x, 0.f); v.y = fmaxf(v.y, 0.f);
            v.z = fmaxf(v.z, 0.f); v.w = fmaxf(v.w, 0.f);
            *(float4*)&act[row][c4 * 4] = v;
        }
    } else {
        const float* base = h0 + (kt - 4) * 64;
        for (int i = t; i < 64 * 16; i += 256) {
            const int row = i >> 4;
            const int c4  = i & 15;
            const float4 v = *(const float4*)(base + row * U + c4 * 4);
            *(float4*)&act[row][c4 * 4] = v;
        }
    }
    // ---- load weight tile: 64 k x 64 cols ----
    {
        const float* wsrc = (kt < 4) ? (lk + (size_t)kt * 64 * 1024)
                                     : (lrk + (size_t)(kt - 4) * 64 * 1024);
        for (int i = t; i < 64 * 16; i += 256) {
            const int row = i >> 4;
            const int c4  = i & 15;
            const float4 w = *(const float4*)(wsrc + (size_t)row * 1024 + ct * 64 + c4 * 4);
            *(float4*)&wt[row][c4 * 4] = w;
        }
    }
    __syncthreads();

    const int c4 = t & 15;       // col group: 4 cols ct*64 + c4*4 ..
    const int bq = t >> 4;       // batches bq, bq+16, bq+32, bq+48
    float s0x = 0.f, s0y = 0.f, s0z = 0.f, s0w = 0.f;
    float s1x = 0.f, s1y = 0.f, s1z = 0.f, s1w = 0.f;
    float s2x = 0.f, s2y = 0.f, s2z = 0.f, s2w = 0.f;
    float s3x = 0.f, s3y = 0.f, s3z = 0.f, s3w = 0.f;

    #pragma unroll 4
    for (int kk = 0; kk < 64; kk++) {
        const float4 w = *(const float4*)&wt[kk][c4 * 4];
        const float a0 = act[bq     ][kk];
        const float a1 = act[bq + 16][kk];
        const float a2 = act[bq + 32][kk];
        const float a3 = act[bq + 48][kk];
        s0x += a0 * w.x; s0y += a0 * w.y; s0z += a0 * w.z; s0w += a0 * w.w;
        s1x += a1 * w.x; s1y += a1 * w.y; s1z += a1 * w.z; s1w += a1 * w.w;
        s2x += a2 * w.x; s2y += a2 * w.y; s2z += a2 * w.z; s2w += a2 * w.w;
        s3x += a3 * w.x; s3y += a3 * w.y; s3z += a3 * w.z; s3w += a3 * w.w;
    }

    // unit-major scatter: global col = ct*64 + c4*4 + q
    // gate gg = ct>>2 (4 ct per gate), unit u = (ct&3)*64 + c4*4 + q
    const int gg = ct >> 2;
    const int u0 = (ct & 3) * 64 + c4 * 4;
    {
        float* d = &g_zp[kt][bq][u0 * 4 + gg];
        d[0] = s0x; d[4] = s0y; d[8] = s0z; d[12] = s0w;
    }
    {
        float* d = &g_zp[kt][bq + 16][u0 * 4 + gg];
        d[0] = s1x; d[4] = s1y; d[8] = s1z; d[12] = s1w;
    }
    {
        float* d = &g_zp[kt][bq + 32][u0 * 4 + gg];
        d[0] = s2x; d[4] = s2y; d[8] = s2z; d[12] = s2w;
    }
    {
        float* d = &g_zp[kt][bq + 48][u0 * 4 + gg];
        d[0] = s3x; d[4] = s3y; d[8] = s3z; d[12] = s3w;
    }
}

// ===========================================================================
// K4: gates. 128 blocks x 128 threads; block = (batch, half), thread = unit.
// Reads 8 float4 partial slices (coalesced), applies LSTM nonlinearity.
// ===========================================================================
__global__ __launch_bounds__(128, 8)
void k4_gates(const float* __restrict__ c0in, const float* __restrict__ lb,
              float* __restrict__ out)
{
    const int b    = blockIdx.x >> 1;
    const int half = blockIdx.x & 1;
    const int u    = half * 128 + threadIdx.x;

    float zi = 0.f, zf = 0.f, zg = 0.f, zo = 0.f;
    #pragma unroll
    for (int kt = 0; kt < 8; kt++) {
        const float4 z = *(const float4*)&g_zp[kt][b][u * 4];
        zi += z.x; zf += z.y; zg += z.z; zo += z.w;
    }
    zi += lb[u];
    zf += lb[U + u];
    zg += lb[2 * U + u];
    zo += lb[3 * U + u];

    const float cprev = c0in[b * U + u];
    const float cn = sigmoidf_(zf) * cprev + sigmoidf_(zi) * tanhf(zg);
    const float hn = sigmoidf_(zo) * tanhf(cn);
    out[b * U + u]         = hn;
    out[B * U + b * U + u] = cn;
}

// ===========================================================================
// K5: nsc1 partial. 128 blocks = 32 unit-tiles (8 units) x 4 k-tiles (64).
// acts = h_new (from out). atomicAdd into g_ns (bias pre-initialized).
// ===========================================================================
__global__ __launch_bounds__(256, 1)
void k5_nsc1(const float* __restrict__ w1, const float* __restrict__ out)
{
    const int ut = blockIdx.x & 31;
    const int kt = blockIdx.x >> 5;      // 0..3, k-slice of 64
    const int t  = threadIdx.x;
    const int k0 = kt * 64;

    __shared__ float axs[64][68];
    __shared__ float wts[64][12];

    for (int i = t; i < 64 * 16; i += 256) {
        const int row = i >> 4;
        const int c4  = i & 15;
        const float4 v = *(const float4*)(out + row * U + k0 + c4 * 4);
        *(float4*)&axs[row][c4 * 4] = v;
    }
    if (t < 128) {
        const int row = t >> 1;
        const int h   = t & 1;
        const float4 w = *(const float4*)(w1 + (size_t)(k0 + row) * U + ut * 8 + h * 4);
        *(float4*)&wts[row][h * 4] = w;
    }
    __syncthreads();

    const int u2 = t & 3;
    const int bp = t >> 2;
    float a0 = 0.f, a1 = 0.f, a2 = 0.f, a3 = 0.f;
    #pragma unroll 4
    for (int k = 0; k < 64; k += 2) {
        const float x0 = axs[bp][k];
        const float x1 = axs[bp][k + 1];
        const float2 w0 = *(const float2*)&wts[k][u2 * 2];
        const float2 w1v = *(const float2*)&wts[k + 1][u2 * 2];
        a0 += x0 * w0.x;  a1 += x0 * w0.y;
        a2 += x1 * w1v.x; a3 += x1 * w1v.y;
    }
    const int u = ut * 8 + u2 * 2;
    atomicAdd(&g_ns[bp * U + u],     a0 + a2);
    atomicAdd(&g_ns[bp * U + u + 1], a1 + a3);
}

// ===========================================================================
// K6: nsc2. next_section = sigmoid(relu(g_ns) @ W2 + b2). 64 blocks x 96.
// ===========================================================================
__global__ __launch_bounds__(96, 8)
void k6_nsc2(const float* __restrict__ w2, const float* __restrict__ b2,
             float* __restrict__ out)
{
    const int b = blockIdx.x;
    const int t = threadIdx.x;
    const int g = t >> 5;
    const int l = t & 31;

    const float* ns = g_ns + b * U;
    float s = 0.0f;
    #pragma unroll
    for (int k = l; k < U; k += 32)
        s += fmaxf(ns[k], 0.0f) * w2[k * 3 + g];
    #pragma unroll
    for (int o = 16; o > 0; o >>= 1)
        s += __shfl_down_sync(0xffffffffu, s, o);
    if (l == 0)
        out[2 * B * U + b * 3 + g] = sigmoidf_(s + b2[g]);
}

// ===========================================================================
extern "C" void kernel_launch(void* const* d_in, const int* in_sizes, int n_in,
                              void* d_out, int out_size)
{
    const float* image   = (const float*)d_in[0];
    const float* section = (const float*)d_in[1];
    const float* h0      = (const float*)d_in[2];
    const float* c0      = (const float*)d_in[3];
    const float* conv1_k = (const float*)d_in[4];
    const float* conv1_b = (const float*)d_in[5];
    const float* conv2_k = (const float*)d_in[6];
    const float* conv2_b = (const float*)d_in[7];
    const float* dense_w = (const float*)d_in[8];
    const float* dense_b = (const float*)d_in[9];
    const float* lstm_k  = (const float*)d_in[10];
    const float* lstm_rk = (const float*)d_in[11];
    const float* lstm_b  = (const float*)d_in[12];
    const float* nsc_w1  = (const float*)d_in[13];
    const float* nsc_b1  = (const float*)d_in[14];
    const float* nsc_w2  = (const float*)d_in[15];
    const float* nsc_b2  = (const float*)d_in[16];
    float* out = (float*)d_out;

    k1_front<<<B, 256>>>(image, section, conv1_k, conv1_b,
                         conv2_k, conv2_b, dense_b, nsc_b1);
    k2_dense<<<128, 256>>>(dense_w);
    k3_lstm<<<128, 256>>>(h0, lstm_k, lstm_rk);
    k4_gates<<<128, 128>>>(c0, lstm_b, out);
    k5_nsc1<<<128, 256>>>(nsc_w1, out);
    k6_nsc2<<<B, 96>>>(nsc_w2, nsc_b2, out);
}